// round 9
// baseline (speedup 1.0000x reference)
#include <cuda_runtime.h>
#include <stdint.h>

// SparseGather: out[m, i, j, c] = inputs[n_m, y0_m + i, x0_m + j, c]
// inputs: (N=4, H=512, W=512, C=64) fp32
// active_block_indices: (M=4096, 3) int32 -> (n, by, bx); y0 = by*16, x0 = bx*16
// out: (M, 16, 16, 64) fp32
//
// Units of 32B chunks (ulonglong4; C=64 fp32 -> 8 chunks per pixel):
//   CU   = 8                     (chunks per pixel)
//   WCU  = 512 * 8 = 4096        (row stride, chunks)
//   HWCU = 512 * WCU             (image stride, chunks)
// One input block row: 16 px * 8 = 128 contiguous chunks (4 KB).
// One output block: 16*128 = 2048 contiguous chunks (64 KB).
//
// R9 = unbundled best-of R5 + R8:
//   - 4 rows/CTA, grid = 4*M, 256 threads  (granularity optimum, R1..R6 sweep)
//   - 256-bit accesses (R8's DRAM%-best ingredient: half the LDG/STG count)
//   - reads:  ld.global.cg.v4.b64  (L2-only, evict-NORMAL -- evict_last
//             thrashed: 170MB pinned footprint > 126MB L2, R8 evidence)
//   - writes: st.global.cs.v4.b64  (evict-first streaming; write-once data)

#define CU   8
#define WCU  (512 * CU)
#define HWCU (512 * WCU)

__device__ __forceinline__ ulonglong4 ldg256_cg(const ulonglong4* p)
{
    ulonglong4 v;
    asm volatile("ld.global.cg.v4.b64 {%0,%1,%2,%3}, [%4];"
                 : "=l"(v.x), "=l"(v.y), "=l"(v.z), "=l"(v.w)
                 : "l"(p));
    return v;
}

__device__ __forceinline__ void stg256_cs(ulonglong4* p, ulonglong4 v)
{
    asm volatile("st.global.cs.v4.b64 [%0], {%1,%2,%3,%4};"
                 :: "l"(p), "l"(v.x), "l"(v.y), "l"(v.z), "l"(v.w)
                 : "memory");
}

__global__ __launch_bounds__(256) void sparse_gather_kernel(
    const ulonglong4* __restrict__ in,
    const int*        __restrict__ idx,
    ulonglong4*       __restrict__ out)
{
    const int b  = blockIdx.x;        // 0 .. 4*M-1
    const int m  = b >> 2;            // block index
    const int r0 = (b & 3) << 2;      // row offset: 0, 4, 8, 12
    const int t  = threadIdx.x;       // 0..255

    const int rA = (t >> 7);          // 0 or 1: first row this thread handles
    const int c  = (t & 127);         // chunk within row

    const int n  = idx[3 * m + 0];
    const int by = idx[3 * m + 1];
    const int bx = idx[3 * m + 2];

    const ulonglong4* src = in
        + (size_t)n * HWCU
        + (size_t)(by * 16 + r0) * WCU
        + (size_t)(bx * 16) * CU;

    ulonglong4* dst = out + (size_t)m * 2048 + (size_t)r0 * 128;

    // rows rA and rA+2 of this quarter-block; each row = 128 contiguous chunks.
    ulonglong4 v0 = ldg256_cg(&src[(size_t)rA * WCU + c]);
    ulonglong4 v1 = ldg256_cg(&src[(size_t)(rA + 2) * WCU + c]);
    stg256_cs(&dst[rA * 128 + c],       v0);
    stg256_cs(&dst[(rA + 2) * 128 + c], v1);
}

extern "C" void kernel_launch(void* const* d_in, const int* in_sizes, int n_in,
                              void* d_out, int out_size)
{
    const ulonglong4* in  = (const ulonglong4*)d_in[0];
    const int*        idx = (const int*)d_in[2];   // active_block_indices
    ulonglong4*       out = (ulonglong4*)d_out;

    const int M = in_sizes[2] / 3;                 // 4096

    sparse_gather_kernel<<<4 * M, 256>>>(in, idx, out);
}

// round 10
// speedup vs baseline: 1.0056x; 1.0056x over previous
#include <cuda_runtime.h>
#include <stdint.h>

// SparseGather: out[m, i, j, c] = inputs[n_m, y0_m + i, x0_m + j, c]
// inputs: (N=4, H=512, W=512, C=64) fp32
// active_block_indices: (M=4096, 3) int32 -> (n, by, bx); y0 = by*16, x0 = bx*16
// out: (M, 16, 16, 64) fp32
//
// R10: bulk-async engine copy (cp.async.bulk), no per-thread LDG/STG at all.
// Work item = quarter-block (4 rows):
//   4x cp.async.bulk  G->S   (4 KB per row; rows 128B-aligned, 128KB apart)
//   1x cp.async.bulk  S->G   (16 KB, fully contiguous output)
// One elected lane per 32-thread CTA issues everything; mbarrier completes
// the loads, bulk_group completes the store. 13 CTAs/SM (16 KB smem each)
// give ~13 overlapped 32KB pipelines per SM.
//
// Byte geometry:
//   ROW_BYTES   = 16 px * 64 ch * 4 B = 4096
//   W_ROW_BYTES = 512 * 64 * 4        = 131072   (input row stride)
//   IMG_BYTES   = 512 * W_ROW_BYTES               (input image stride)
//   QBLK_BYTES  = 4 * ROW_BYTES       = 16384     (quarter-block)

#define ROW_BYTES   4096
#define W_ROW_BYTES (512 * 64 * 4)
#define IMG_BYTES   ((size_t)512 * W_ROW_BYTES)
#define QBLK_BYTES  (4 * ROW_BYTES)

__device__ __forceinline__ uint32_t smem_u32(const void* p)
{
    uint32_t a;
    asm("{ .reg .u64 t; cvta.to.shared.u64 t, %1; cvt.u32.u64 %0, t; }"
        : "=r"(a) : "l"(p));
    return a;
}

__global__ __launch_bounds__(32) void sparse_gather_kernel(
    const char* __restrict__ in,
    const int*  __restrict__ idx,
    char*       __restrict__ out)
{
    __shared__ __align__(128) char buf[QBLK_BYTES];
    __shared__ __align__(8)  uint64_t mbar;

    if (threadIdx.x == 0) {
        const int b  = blockIdx.x;        // 0 .. 4*M-1
        const int m  = b >> 2;            // block index
        const int r0 = (b & 3) << 2;      // row offset: 0, 4, 8, 12

        const int n  = idx[3 * m + 0];
        const int by = idx[3 * m + 1];
        const int bx = idx[3 * m + 2];

        const char* src = in
            + (size_t)n * IMG_BYTES
            + (size_t)(by * 16 + r0) * W_ROW_BYTES
            + (size_t)(bx * 16) * 256;           // 16 px * 64 ch * 4 B / px-row

        char* dst = out + (size_t)m * (16 * ROW_BYTES) + (size_t)r0 * ROW_BYTES;

        const uint32_t s_buf  = smem_u32(buf);
        const uint32_t s_mbar = smem_u32(&mbar);

        // init mbarrier (count 1: the expect_tx arrive) + make it visible to
        // the async proxy before TMA references it.
        asm volatile("mbarrier.init.shared.b64 [%0], 1;" :: "r"(s_mbar) : "memory");
        asm volatile("fence.proxy.async.shared::cta;" ::: "memory");

        asm volatile("mbarrier.arrive.expect_tx.shared.b64 _, [%0], %1;"
                     :: "r"(s_mbar), "r"((uint32_t)QBLK_BYTES) : "memory");

        #pragma unroll
        for (int r = 0; r < 4; ++r) {
            asm volatile(
                "cp.async.bulk.shared::cta.global.mbarrier::complete_tx::bytes "
                "[%0], [%1], %2, [%3];"
                :: "r"(s_buf + r * ROW_BYTES),
                   "l"(src + (size_t)r * W_ROW_BYTES),
                   "r"((uint32_t)ROW_BYTES),
                   "r"(s_mbar)
                : "memory");
        }

        // wait for all 16 KB to land (phase 0)
        {
            uint32_t done;
            asm volatile(
                "{\n\t"
                ".reg .pred p;\n\t"
                "mbarrier.try_wait.parity.shared.b64 p, [%1], 0;\n\t"
                "selp.b32 %0, 1, 0, p;\n\t"
                "}"
                : "=r"(done) : "r"(s_mbar) : "memory");
            while (!done) {
                asm volatile(
                    "{\n\t"
                    ".reg .pred p;\n\t"
                    "mbarrier.try_wait.parity.shared.b64 p, [%1], 0, 0x989680;\n\t"
                    "selp.b32 %0, 1, 0, p;\n\t"
                    "}"
                    : "=r"(done) : "r"(s_mbar) : "memory");
            }
        }

        // one contiguous 16 KB bulk store
        asm volatile(
            "cp.async.bulk.global.shared::cta.bulk_group [%0], [%1], %2;"
            :: "l"(dst), "r"(s_buf), "r"((uint32_t)QBLK_BYTES)
            : "memory");
        asm volatile("cp.async.bulk.commit_group;" ::: "memory");
        asm volatile("cp.async.bulk.wait_group.read 0;" ::: "memory");
    }
}

extern "C" void kernel_launch(void* const* d_in, const int* in_sizes, int n_in,
                              void* d_out, int out_size)
{
    const char* in  = (const char*)d_in[0];
    const int*  idx = (const int*)d_in[2];   // active_block_indices
    char*       out = (char*)d_out;

    const int M = in_sizes[2] / 3;           // 4096

    sparse_gather_kernel<<<4 * M, 32>>>(in, idx, out);
}

// round 11
// speedup vs baseline: 1.0204x; 1.0147x over previous
#include <cuda_runtime.h>
#include <stdint.h>

// SparseGather: out[m, i, j, c] = inputs[n_m, y0_m + i, x0_m + j, c]
// inputs: (N=4, H=512, W=512, C=64) fp32
// active_block_indices: (M=4096, 3) int32 -> (n, by, bx); y0 = by*16, x0 = bx*16
// out: (M, 16, 16, 64) fp32
//
// FINAL (= R5, measured best of the 10-round study):
//   Traffic is at the mandatory floor: 268 MB output writes + ~175 MB
//   unique-block reads (duplicate blocks fully L2-deduped). Five independent
//   movement mechanisms (128b/256b LSU, cg/cs/evict_last policies, persistent
//   grid, TMA cp.async.bulk) all plateau at ~6.05-6.15 TB/s => the limit is
//   the mixed ~60/40 W/R DRAM stream + LTS path, not the SM side.
//   Best point: 4 rows/CTA (granularity sweep optimum), 128-bit __ldcg reads
//   (L2-only, no L1 allocate -- zero intra-SM reuse), __stcs streaming stores
//   (evict-first; the write stream must not evict reusable input in L2).
//
// Units of float4 (C=64 -> 16 float4 per pixel):
//   C4   = 16
//   WC4  = 512 * 16 = 8192   (row stride, float4)
//   HWC4 = 512 * WC4         (image stride, float4)

#define C4   16
#define WC4  (512 * C4)
#define HWC4 (512 * WC4)

__global__ __launch_bounds__(256) void sparse_gather_kernel(
    const float4* __restrict__ in,
    const int*    __restrict__ idx,
    float4*       __restrict__ out)
{
    const int b  = blockIdx.x;     // 0 .. 4*M-1
    const int m  = b >> 2;         // block index
    const int r0 = (b & 3) << 2;   // row offset: 0, 4, 8, 12
    const int t  = threadIdx.x;    // 0..255

    const int n  = idx[3 * m + 0];
    const int by = idx[3 * m + 1];
    const int bx = idx[3 * m + 2];

    const float4* src = in
        + (size_t)n * HWC4
        + (size_t)(by * 16 + r0) * WC4
        + (size_t)(bx * 16) * C4;

    float4* dst = out + (size_t)m * 4096 + (size_t)r0 * 256;

    // 4 rows; each row = 256 contiguous float4 on both sides.
    float4 v[4];
    #pragma unroll
    for (int r = 0; r < 4; ++r) {
        v[r] = __ldcg(&src[(size_t)r * WC4 + t]);   // L2-only read
    }
    #pragma unroll
    for (int r = 0; r < 4; ++r) {
        __stcs(&dst[r * 256 + t], v[r]);            // streaming store
    }
}

extern "C" void kernel_launch(void* const* d_in, const int* in_sizes, int n_in,
                              void* d_out, int out_size)
{
    const float4* in  = (const float4*)d_in[0];
    const int*    idx = (const int*)d_in[2];   // active_block_indices
    float4*       out = (float4*)d_out;

    const int M = in_sizes[2] / 3;             // 4096

    sparse_gather_kernel<<<4 * M, 256>>>(in, idx, out);
}

// round 12
// speedup vs baseline: 1.0258x; 1.0053x over previous
#include <cuda_runtime.h>
#include <stdint.h>

// SparseGather: out[m, i, j, c] = inputs[n_m, y0_m + i, x0_m + j, c]
// inputs: (N=4, H=512, W=512, C=64) fp32
// active_block_indices: (M=4096, 3) int32 -> (n, by, bx); y0 = by*16, x0 = bx*16
// out: (M, 16, 16, 64) fp32
//
// FINAL — converged optimum of the 11-round study:
//   * Traffic at mandatory floor: 268 MB writes + ~175 MB unique-block reads
//     (duplicates fully L2-deduped).
//   * Ceiling is mechanism-independent: 128b/256b LSU, cg/cs/evict_last,
//     persistent grid, and TMA cp.async.bulk all plateau at 6.05-6.15 TB/s
//     => mixed ~60/40 W/R DRAM stream is the limiter, not the SM path.
//   * Granularity sweep (16/8/4/2 rows per CTA -> 75.3/76.1/76.9/75.2 DRAM%)
//     fixes 4 rows/CTA as the optimum.
//   Best measured: 72.6-72.8 us ncu, 78.3-78.6 us wall, rel_err 0.
//
// Units of float4 (C=64 -> 16 float4 per pixel):
//   C4   = 16
//   WC4  = 512 * 16 = 8192   (row stride, float4)
//   HWC4 = 512 * WC4         (image stride, float4)

#define C4   16
#define WC4  (512 * C4)
#define HWC4 (512 * WC4)

__global__ __launch_bounds__(256) void sparse_gather_kernel(
    const float4* __restrict__ in,
    const int*    __restrict__ idx,
    float4*       __restrict__ out)
{
    const int b  = blockIdx.x;     // 0 .. 4*M-1
    const int m  = b >> 2;         // block index
    const int r0 = (b & 3) << 2;   // row offset: 0, 4, 8, 12
    const int t  = threadIdx.x;    // 0..255

    const int n  = idx[3 * m + 0];
    const int by = idx[3 * m + 1];
    const int bx = idx[3 * m + 2];

    const float4* src = in
        + (size_t)n * HWC4
        + (size_t)(by * 16 + r0) * WC4
        + (size_t)(bx * 16) * C4;

    float4* dst = out + (size_t)m * 4096 + (size_t)r0 * 256;

    // 4 rows; each row = 256 contiguous float4 on both sides.
    float4 v[4];
    #pragma unroll
    for (int r = 0; r < 4; ++r) {
        v[r] = __ldcg(&src[(size_t)r * WC4 + t]);   // L2-only read (no L1 alloc)
    }
    #pragma unroll
    for (int r = 0; r < 4; ++r) {
        __stcs(&dst[r * 256 + t], v[r]);            // evict-first streaming store
    }
}

extern "C" void kernel_launch(void* const* d_in, const int* in_sizes, int n_in,
                              void* d_out, int out_size)
{
    const float4* in  = (const float4*)d_in[0];
    const int*    idx = (const int*)d_in[2];   // active_block_indices
    float4*       out = (float4*)d_out;

    const int M = in_sizes[2] / 3;             // 4096

    sparse_gather_kernel<<<4 * M, 256>>>(in, idx, out);
}